// round 6
// baseline (speedup 1.0000x reference)
#include <cuda_runtime.h>

// DiscriminativeLoss: B=8, E=16, N=512*512, C<=32
// R5: pass1 with 2 blocks/SM (TPX=512) to overlap phase barriers with
// cp.async prefetch; match_any-aggregated shared atomics; finalize fused
// into pass2 via last-block pattern.
// K0 zero -> K1 pass1 (sorted segment sums) -> K2 pass2 (+inline finalize).

namespace {
constexpr int B_ = 8;
constexpr int E_ = 16;
constexpr int NSHIFT = 18;        // N = 2^18 pixels per batch
constexpr int N_ = 1 << NSHIFT;
constexpr int N4_ = N_ / 4;
constexpr int N4SHIFT = 16;
constexpr int CMAX = 32;
constexpr int CS = 33;            // labels 0..32 (0 = background)
constexpr float DVAR = 0.5f;
constexpr float TWO_DDIST = 3.0f;
constexpr float GAMMA_ = 0.001f;

// pass1 tiling: 512-pixel tiles, one pixel per thread
constexpr int TPX = 512;
constexpr int ESTRIDE = 516;                 // padded floats per dim row
constexpr int T1 = 512;
constexpr int TILES_PER_B = N_ / TPX;        // 512
constexpr int NTILES = B_ * TILES_PER_B;     // 4096
constexpr int GRID1 = 296;                   // 2 blocks per SM
// dynamic smem layout (floats)
constexpr int EMB_BUF_F = E_ * ESTRIDE;      // 8256
constexpr int LAB_OFF_F = 2 * EMB_BUF_F;     // 16512 (2 emb buffers)
constexpr int SORT_OFF_F = LAB_OFF_F + 2 * TPX;   // 2 int label buffers
constexpr int HIST_OFF_F = SORT_OFF_F + TPX / 2;  // u16 sorted list
constexpr int SMEM1_FLOATS = HIST_OFF_F + 3 * CS + 8;
constexpr int SMEM1_BYTES = SMEM1_FLOATS * 4;     // ~71.6 KB

constexpr int GRID2 = B_ * N4_ / 256;        // 2048
}

__device__ __align__(16) float g_sums[B_ * CS * E_];
__device__ float g_cnt[B_ * CS];
__device__ float g_hinge[B_ * CS];
__device__ unsigned g_done;

__device__ __forceinline__ void red_add_v4(float* a, float x, float y, float z, float w) {
    asm volatile("red.global.add.v4.f32 [%0], {%1,%2,%3,%4};"
                 :: "l"(a), "f"(x), "f"(y), "f"(z), "f"(w) : "memory");
}
__device__ __forceinline__ void red_add(float* a, float v) {
    asm volatile("red.global.add.f32 [%0], %1;" :: "l"(a), "f"(v) : "memory");
}
__device__ __forceinline__ void cp16(unsigned dst, const void* src) {
    asm volatile("cp.async.cg.shared.global [%0], [%1], 16;" :: "r"(dst), "l"(src));
}
__device__ __forceinline__ unsigned smem_u32(const void* p) {
    unsigned a;
    asm("{ .reg .u64 t; cvta.to.shared.u64 t, %1; cvt.u32.u64 %0, t; }" : "=r"(a) : "l"(p));
    return a;
}
__device__ __forceinline__ float wred(float v) {
#pragma unroll
    for (int o = 16; o; o >>= 1) v += __shfl_xor_sync(0xffffffffu, v, o);
    return v;
}

__global__ void k_zero() {
    for (int i = threadIdx.x; i < B_ * CS * E_; i += blockDim.x) g_sums[i] = 0.f;
    int i = threadIdx.x;
    if (i < B_ * CS) { g_cnt[i] = 0.f; g_hinge[i] = 0.f; }
    if (i == 0) g_done = 0u;
}

// ---------------- Pass 1: sorted segment sums ----------------
__global__ void __launch_bounds__(T1) k_pass1(const float* __restrict__ emb,
                                              const int* __restrict__ mask) {
    extern __shared__ float sm[];
    int* labS = (int*)(sm + LAB_OFF_F);
    unsigned short* sortedS = (unsigned short*)(sm + SORT_OFF_F);
    int* shist = (int*)(sm + HIST_OFF_F);
    int* soff = shist + CS;
    int* scur = soff + CS;

    const int tid = threadIdx.x;
    const int lane = tid & 31;
    const int wid = tid >> 5;
    const unsigned smem_base = smem_u32(sm);
    const int t0 = blockIdx.x;

    auto prefetch = [&](int t, int buf) {
        int b = t >> 9;                           // TILES_PER_B = 512
        int gp0 = (t & (TILES_PER_B - 1)) << 9;   // pixel offset in batch
        const float* ebase = emb + (((size_t)b * E_) << NSHIFT) + gp0;
#pragma unroll
        for (int k = 0; k < 4; k++) {
            int c = tid + k * T1;                 // 0..2047
            int e = c >> 7, i4 = (c & 127) << 2;
            cp16(smem_base + (unsigned)(buf * EMB_BUF_F + e * ESTRIDE + i4) * 4u,
                 ebase + ((size_t)e << NSHIFT) + i4);
        }
        const int* lbase = mask + ((size_t)b << NSHIFT) + gp0;
        if (tid < TPX / 4)
            cp16(smem_base + (unsigned)(LAB_OFF_F + buf * TPX + tid * 4) * 4u,
                 lbase + tid * 4);
        asm volatile("cp.async.commit_group;" ::: "memory");
    };

    int nt = 0;
    for (int t = t0; t < NTILES; t += GRID1) nt++;
    if (nt == 0) return;

    prefetch(t0, 0);

    for (int k = 0; k < nt; k++) {
        int t = t0 + k * GRID1;
        int buf = k & 1;
        bool more = (k + 1) < nt;
        if (more) prefetch(t + GRID1, buf ^ 1);
        if (more) { asm volatile("cp.async.wait_group 1;" ::: "memory"); }
        else      { asm volatile("cp.async.wait_group 0;" ::: "memory"); }
        if (tid < CS) shist[tid] = 0;
        __syncthreads();

        int b = t >> 9;
        const float* eb = sm + buf * EMB_BUF_F;
        int l0 = labS[buf * TPX + tid];

        // histogram: one aggregated ATOMS per distinct label per warp
        unsigned mm = __match_any_sync(0xffffffffu, l0);
        int leader = __ffs(mm) - 1;
        int mcnt = __popc(mm);
        int rank = __popc(mm & ((1u << lane) - 1u));
        if (l0 > 0 && lane == leader) atomicAdd(&shist[l0], mcnt);
        __syncthreads();

        // scan (warp 0: labels 1..32 on lanes 0..31) + count reds
        if (wid == 0) {
            int c = shist[lane + 1];
            int inc = c;
#pragma unroll
            for (int o = 1; o < 32; o <<= 1) {
                int v = __shfl_up_sync(0xffffffffu, inc, o);
                if (lane >= o) inc += v;
            }
            int start = inc - c;
            soff[lane + 1] = start;
            scur[lane + 1] = start;
            if (c > 0) red_add(&g_cnt[b * CS + lane + 1], (float)c);
        }
        __syncthreads();

        // scatter with warp aggregation (leader grabs a base, lanes take rank)
        int base = 0;
        if (l0 > 0 && lane == leader) base = atomicAdd(&scur[l0], mcnt);
        base = __shfl_sync(0xffffffffu, base, leader);
        if (l0 > 0) sortedS[base + rank] = (unsigned short)tid;
        __syncthreads();

        // gather + accumulate: warp w owns labels 2w+1, 2w+2
#pragma unroll
        for (int li = 0; li < 2; li++) {
            int l = 2 * wid + 1 + li;
            int m = shist[l];
            int start = soff[l];
            float acc[E_];
#pragma unroll
            for (int e = 0; e < E_; e++) acc[e] = 0.f;
            for (int p = lane; p < m; p += 32) {
                int idx = sortedS[start + p];
                const float* px = eb + idx;
#pragma unroll
                for (int e = 0; e < E_; e++) acc[e] += px[e * ESTRIDE];
            }
#pragma unroll
            for (int o = 16; o; o >>= 1) {
#pragma unroll
                for (int e = 0; e < E_; e++)
                    acc[e] += __shfl_xor_sync(0xffffffffu, acc[e], o);
            }
            if (lane == 0 && m > 0) {
                float* dst = &g_sums[(b * CS + l) * E_];
                red_add_v4(dst + 0, acc[0], acc[1], acc[2], acc[3]);
                red_add_v4(dst + 4, acc[4], acc[5], acc[6], acc[7]);
                red_add_v4(dst + 8, acc[8], acc[9], acc[10], acc[11]);
                red_add_v4(dst + 12, acc[12], acc[13], acc[14], acc[15]);
            }
        }
        __syncthreads();   // protect sort arrays + emb buffer for reuse
    }
}

// ---------------- finalize (inlined into last pass2 block) ----------------
__device__ void do_finalize(const int* __restrict__ ninst,
                            float* __restrict__ out, int out_size) {
    __shared__ float cents[B_][CMAX][E_ + 1];
    __shared__ float part[B_][4];
    int C = *ninst; if (C > CMAX) C = CMAX;
    int lane = threadIdx.x & 31;
    int b = threadIdx.x >> 5;

    float cnt = (lane < C) ? g_cnt[b * CS + lane + 1] : 0.f;
    bool pres = cnt > 0.f;
    float safe = fmaxf(cnt, 1.f);

    float ce[E_];
    float ss = 0.f;
#pragma unroll
    for (int e = 0; e < E_; e++) {
        float v = (lane < C) ? g_sums[(b * CS + lane + 1) * E_ + e] / safe : 0.f;
        ce[e] = v;
        cents[b][lane][e] = v;
        ss = fmaf(v, v, ss);
    }
    unsigned pmask = __ballot_sync(0xffffffffu, pres);
    int npres = __popc(pmask);
    float hv = pres ? g_hinge[b * CS + lane + 1] / safe : 0.f;
    float rg = pres ? sqrtf(ss) : 0.f;
    __syncwarp();

    float ph = 0.f, np = 0.f;
    if (pres) {
        for (int c2 = lane + 1; c2 < C; c2++) {
            if ((pmask >> c2) & 1u) {
                float pss = 0.f;
#pragma unroll
                for (int e = 0; e < E_; e++) {
                    float d = ce[e] - cents[b][c2][e];
                    pss = fmaf(d, d, pss);
                }
                float h = TWO_DDIST - sqrtf(pss);
                if (h > 0.f) ph += h * h;
                np += 1.f;
            }
        }
    }
    hv = wred(hv); rg = wred(rg); ph = wred(ph); np = wred(np);

    if (lane == 0) {
        float nv = (float)npres;
        part[b][0] = (npres > 0) ? hv / nv : 0.f;
        part[b][1] = (np > 0.f) ? ph / np : 0.f;
        part[b][2] = (npres > 0) ? rg / nv : 0.f;
        part[b][3] = (npres > 0) ? 1.f : 0.f;
    }
    __syncthreads();
    if (threadIdx.x == 0) {
        float sv = 0.f, sd = 0.f, sr = 0.f, vb = 0.f;
        for (int bb = 0; bb < B_; bb++) {
            sv += part[bb][0] * part[bb][3];
            sd += part[bb][1] * part[bb][3];
            sr += part[bb][2] * part[bb][3];
            vb += part[bb][3];
        }
        float den = fmaxf(vb, 1.f);
        float lv = (vb > 0.f) ? sv / den : 0.f;
        float ld = (vb > 0.f) ? sd / den : 0.f;
        float lr = (vb > 0.f) ? sr / den : 0.f;
        float tot = lv + ld + GAMMA_ * lr;
        out[0] = tot;
        if (out_size > 1) out[1] = lv;
        if (out_size > 2) out[2] = ld;
        if (out_size > 3) out[3] = lr;
    }
}

// ---------------- Pass 2: hinged variance + fused finalize ----------------
__global__ void __launch_bounds__(256) k_pass2(const float4* __restrict__ emb,
                                               const int4* __restrict__ mask,
                                               const int* __restrict__ ninst,
                                               float* __restrict__ out, int out_size) {
    __shared__ float csh[CS * 17];
    __shared__ float shinge[CS];
    __shared__ int is_last;
    int idx = blockIdx.x * blockDim.x + threadIdx.x;
    int b = idx >> N4SHIFT;   // constant per block

    if (threadIdx.x < CS) shinge[threadIdx.x] = 0.f;
    for (int i = threadIdx.x; i < CS * E_; i += blockDim.x) {
        int l = i >> 4, e = i & 15;
        csh[l * 17 + e] = g_sums[(b * CS + l) * E_ + e] / fmaxf(g_cnt[b * CS + l], 1.f);
    }
    __syncthreads();

    int n4 = idx & (N4_ - 1);
    int4 lab = mask[idx];
    const float4* ep = emb + (((size_t)b * E_) << N4SHIFT) + n4;

    const float* cx = &csh[lab.x * 17];
    const float* cy = &csh[lab.y * 17];
    const float* cz = &csh[lab.z * 17];
    const float* cw = &csh[lab.w * 17];

    float ssx = 0.f, ssy = 0.f, ssz = 0.f, ssw = 0.f;
#pragma unroll
    for (int e = 0; e < E_; e++) {
        float4 q = ep[(size_t)e << N4SHIFT];
        float dx = q.x - cx[e]; ssx = fmaf(dx, dx, ssx);
        float dy = q.y - cy[e]; ssy = fmaf(dy, dy, ssy);
        float dz = q.z - cz[e]; ssz = fmaf(dz, dz, ssz);
        float dw = q.w - cw[e]; ssw = fmaf(dw, dw, ssw);
    }
    if (lab.x > 0) { float h = sqrtf(ssx) - DVAR; if (h > 0.f) atomicAdd(&shinge[lab.x], h * h); }
    if (lab.y > 0) { float h = sqrtf(ssy) - DVAR; if (h > 0.f) atomicAdd(&shinge[lab.y], h * h); }
    if (lab.z > 0) { float h = sqrtf(ssz) - DVAR; if (h > 0.f) atomicAdd(&shinge[lab.z], h * h); }
    if (lab.w > 0) { float h = sqrtf(ssw) - DVAR; if (h > 0.f) atomicAdd(&shinge[lab.w], h * h); }
    __syncthreads();
    if (threadIdx.x < CS && shinge[threadIdx.x] != 0.f)
        red_add(&g_hinge[b * CS + threadIdx.x], shinge[threadIdx.x]);

    // last block runs finalize
    __syncthreads();
    if (threadIdx.x == 0) {
        __threadfence();
        unsigned v = atomicAdd(&g_done, 1u);
        is_last = (v == (unsigned)(GRID2 - 1));
    }
    __syncthreads();
    if (is_last) {
        __threadfence();
        do_finalize(ninst, out, out_size);
    }
}

extern "C" void kernel_launch(void* const* d_in, const int* in_sizes, int n_in,
                              void* d_out, int out_size) {
    const float* emb = (const float*)d_in[0];
    const int* mask = (const int*)d_in[1];
    const int* ninst = (const int*)d_in[2];
    (void)in_sizes; (void)n_in;

    cudaFuncSetAttribute(k_pass1, cudaFuncAttributeMaxDynamicSharedMemorySize, SMEM1_BYTES);

    k_zero<<<1, 512>>>();
    k_pass1<<<GRID1, T1, SMEM1_BYTES>>>(emb, mask);
    k_pass2<<<GRID2, 256>>>((const float4*)emb, (const int4*)mask,
                            ninst, (float*)d_out, out_size);
}

// round 7
// speedup vs baseline: 1.4402x; 1.4402x over previous
#include <cuda_runtime.h>

// DiscriminativeLoss: B=8, E=16, N=512*512, C<=32
// R6: pass1 with batch-resident blocks + persistent register accumulators
// (no per-tile shuffle reduction / REDs). TPX=1024, 1 block/SM.
// K0 zero -> K1 pass1 -> K2 pass2 (+fused finalize).

namespace {
constexpr int B_ = 8;
constexpr int E_ = 16;
constexpr int NSHIFT = 18;        // N = 2^18 pixels per batch
constexpr int N_ = 1 << NSHIFT;
constexpr int N4_ = N_ / 4;
constexpr int N4SHIFT = 16;
constexpr int CMAX = 32;
constexpr int CS = 33;            // labels 0..32 (0 = background)
constexpr float DVAR = 0.5f;
constexpr float TWO_DDIST = 3.0f;
constexpr float GAMMA_ = 0.001f;

// pass1 tiling
constexpr int TPX = 1024;                    // pixels per tile
constexpr int ESTRIDE = 1028;                // padded floats per dim row
constexpr int T1 = 512;                      // pass1 threads (2 px/thread)
constexpr int TILES_PER_B = N_ / TPX;        // 256
constexpr int BPB = 18;                      // blocks per batch
constexpr int GRID1 = B_ * BPB;              // 144
// chunking: first 4 blocks of each batch take 15 tiles, rest 14 (4*15+14*14=256)
// dynamic smem layout (floats)
constexpr int EMB_BUF_F = E_ * ESTRIDE;      // 16448 per buffer
constexpr int LAB_OFF_F = 2 * EMB_BUF_F;
constexpr int SORT_OFF_F = LAB_OFF_F + 2 * TPX;
constexpr int HIST_OFF_F = SORT_OFF_F + TPX / 2;
constexpr int SMEM1_FLOATS = HIST_OFF_F + 4 * CS + 8;
constexpr int SMEM1_BYTES = SMEM1_FLOATS * 4;   // ~142.7 KB

constexpr int GRID2 = B_ * N4_ / 256;        // 2048
}

__device__ __align__(16) float g_sums[B_ * CS * E_];
__device__ float g_cnt[B_ * CS];
__device__ float g_hinge[B_ * CS];
__device__ unsigned g_done;

__device__ __forceinline__ void red_add_v4(float* a, float x, float y, float z, float w) {
    asm volatile("red.global.add.v4.f32 [%0], {%1,%2,%3,%4};"
                 :: "l"(a), "f"(x), "f"(y), "f"(z), "f"(w) : "memory");
}
__device__ __forceinline__ void red_add(float* a, float v) {
    asm volatile("red.global.add.f32 [%0], %1;" :: "l"(a), "f"(v) : "memory");
}
__device__ __forceinline__ void cp16(unsigned dst, const void* src) {
    asm volatile("cp.async.cg.shared.global [%0], [%1], 16;" :: "r"(dst), "l"(src));
}
__device__ __forceinline__ unsigned smem_u32(const void* p) {
    unsigned a;
    asm("{ .reg .u64 t; cvta.to.shared.u64 t, %1; cvt.u32.u64 %0, t; }" : "=r"(a) : "l"(p));
    return a;
}
__device__ __forceinline__ float wred(float v) {
#pragma unroll
    for (int o = 16; o; o >>= 1) v += __shfl_xor_sync(0xffffffffu, v, o);
    return v;
}

__global__ void k_zero() {
    for (int i = threadIdx.x; i < B_ * CS * E_; i += blockDim.x) g_sums[i] = 0.f;
    int i = threadIdx.x;
    if (i < B_ * CS) { g_cnt[i] = 0.f; g_hinge[i] = 0.f; }
    if (i == 0) g_done = 0u;
}

// ---------------- Pass 1: sorted segment sums, persistent accumulators ----------------
__global__ void __launch_bounds__(T1) k_pass1(const float* __restrict__ emb,
                                              const int* __restrict__ mask) {
    extern __shared__ float sm[];
    int* labS = (int*)(sm + LAB_OFF_F);
    unsigned short* sortedS = (unsigned short*)(sm + SORT_OFF_F);
    int* shist = (int*)(sm + HIST_OFF_F);
    int* soff = shist + CS;
    int* scur = soff + CS;
    int* ctot = scur + CS;

    const int tid = threadIdx.x;
    const int lane = tid & 31;
    const int wid = tid >> 5;
    const unsigned smem_base = smem_u32(sm);

    const int b = blockIdx.x / BPB;
    const int chunk = blockIdx.x % BPB;
    const int nt = 14 + (chunk < 4 ? 1 : 0);
    const int tstart = chunk * 14 + (chunk < 4 ? chunk : 4);

    auto prefetch = [&](int tt, int buf) {
        int gp0 = tt << 10;
        const float* ebase = emb + (((size_t)b * E_) << NSHIFT) + gp0;
#pragma unroll
        for (int k2 = 0; k2 < 8; k2++) {
            int c = tid + k2 * T1;                // 0..4095
            int e = c >> 8, i4 = (c & 255) << 2;
            cp16(smem_base + (unsigned)(buf * EMB_BUF_F + e * ESTRIDE + i4) * 4u,
                 ebase + ((size_t)e << NSHIFT) + i4);
        }
        const int* lbase = mask + ((size_t)b << NSHIFT) + gp0;
        if (tid < TPX / 4)
            cp16(smem_base + (unsigned)(LAB_OFF_F + buf * TPX + tid * 4) * 4u,
                 lbase + tid * 4);
        asm volatile("cp.async.commit_group;" ::: "memory");
    };

    if (wid == 0) ctot[lane] = 0;                 // counts for labels 1..32
    float acc0[E_], acc1[E_];
#pragma unroll
    for (int e = 0; e < E_; e++) { acc0[e] = 0.f; acc1[e] = 0.f; }
    const int la = 2 * wid + 1;                   // labels owned by this warp
    const int lb = 2 * wid + 2;

    prefetch(tstart, 0);

    for (int k = 0; k < nt; k++) {
        int buf = k & 1;
        if (k + 1 < nt) {
            prefetch(tstart + k + 1, buf ^ 1);
            asm volatile("cp.async.wait_group 1;" ::: "memory");
        } else {
            asm volatile("cp.async.wait_group 0;" ::: "memory");
        }
        if (tid < CS) shist[tid] = 0;
        __syncthreads();

        const float* eb = sm + buf * EMB_BUF_F;
        int l0 = labS[buf * TPX + tid];
        int l1 = labS[buf * TPX + tid + T1];

        // histogram: one aggregated ATOMS per distinct label per warp
        unsigned m0 = __match_any_sync(0xffffffffu, l0);
        int lead0 = __ffs(m0) - 1, cnt0 = __popc(m0), rk0 = __popc(m0 & ((1u << lane) - 1u));
        if (l0 > 0 && lane == lead0) atomicAdd(&shist[l0], cnt0);
        unsigned m1 = __match_any_sync(0xffffffffu, l1);
        int lead1 = __ffs(m1) - 1, cnt1 = __popc(m1), rk1 = __popc(m1 & ((1u << lane) - 1u));
        if (l1 > 0 && lane == lead1) atomicAdd(&shist[l1], cnt1);
        __syncthreads();

        // scan (warp 0: labels 1..32 on lanes 0..31) + count accumulation
        if (wid == 0) {
            int c = shist[lane + 1];
            ctot[lane] += c;
            int inc = c;
#pragma unroll
            for (int o = 1; o < 32; o <<= 1) {
                int v = __shfl_up_sync(0xffffffffu, inc, o);
                if (lane >= o) inc += v;
            }
            int start = inc - c;
            soff[lane + 1] = start;
            scur[lane + 1] = start;
        }
        __syncthreads();

        // scatter (warp-aggregated)
        int base0 = 0;
        if (l0 > 0 && lane == lead0) base0 = atomicAdd(&scur[l0], cnt0);
        base0 = __shfl_sync(0xffffffffu, base0, lead0);
        if (l0 > 0) sortedS[base0 + rk0] = (unsigned short)tid;
        int base1 = 0;
        if (l1 > 0 && lane == lead1) base1 = atomicAdd(&scur[l1], cnt1);
        base1 = __shfl_sync(0xffffffffu, base1, lead1);
        if (l1 > 0) sortedS[base1 + rk1] = (unsigned short)(tid + T1);
        __syncthreads();

        // gather into persistent per-lane accumulators (no reduction here)
        {
            int m = shist[la], st = soff[la];
            for (int p = lane; p < m; p += 32) {
                const float* px = eb + sortedS[st + p];
#pragma unroll
                for (int e = 0; e < E_; e++) acc0[e] += px[e * ESTRIDE];
            }
        }
        {
            int m = shist[lb], st = soff[lb];
            for (int p = lane; p < m; p += 32) {
                const float* px = eb + sortedS[st + p];
#pragma unroll
                for (int e = 0; e < E_; e++) acc1[e] += px[e * ESTRIDE];
            }
        }
        __syncthreads();   // protect sort arrays + emb buffer for reuse
    }

    // one reduction + emission per block
#pragma unroll
    for (int o = 16; o; o >>= 1) {
#pragma unroll
        for (int e = 0; e < E_; e++) {
            acc0[e] += __shfl_xor_sync(0xffffffffu, acc0[e], o);
            acc1[e] += __shfl_xor_sync(0xffffffffu, acc1[e], o);
        }
    }
    if (lane == 0) {
        float* d0 = &g_sums[(b * CS + la) * E_];
        red_add_v4(d0 + 0, acc0[0], acc0[1], acc0[2], acc0[3]);
        red_add_v4(d0 + 4, acc0[4], acc0[5], acc0[6], acc0[7]);
        red_add_v4(d0 + 8, acc0[8], acc0[9], acc0[10], acc0[11]);
        red_add_v4(d0 + 12, acc0[12], acc0[13], acc0[14], acc0[15]);
        float* d1 = &g_sums[(b * CS + lb) * E_];
        red_add_v4(d1 + 0, acc1[0], acc1[1], acc1[2], acc1[3]);
        red_add_v4(d1 + 4, acc1[4], acc1[5], acc1[6], acc1[7]);
        red_add_v4(d1 + 8, acc1[8], acc1[9], acc1[10], acc1[11]);
        red_add_v4(d1 + 12, acc1[12], acc1[13], acc1[14], acc1[15]);
    }
    if (wid == 0 && ctot[lane] > 0)
        red_add(&g_cnt[b * CS + lane + 1], (float)ctot[lane]);
}

// ---------------- finalize (runs in last pass2 block) ----------------
__device__ void do_finalize(const int* __restrict__ ninst,
                            float* __restrict__ out, int out_size) {
    __shared__ float cents[B_][CMAX][E_ + 1];
    __shared__ float part[B_][4];
    int C = *ninst; if (C > CMAX) C = CMAX;
    int lane = threadIdx.x & 31;
    int b = threadIdx.x >> 5;

    float cnt = (lane < C) ? g_cnt[b * CS + lane + 1] : 0.f;
    bool pres = cnt > 0.f;
    float safe = fmaxf(cnt, 1.f);

    float ce[E_];
    float ss = 0.f;
#pragma unroll
    for (int e = 0; e < E_; e++) {
        float v = (lane < C) ? g_sums[(b * CS + lane + 1) * E_ + e] / safe : 0.f;
        ce[e] = v;
        cents[b][lane][e] = v;
        ss = fmaf(v, v, ss);
    }
    unsigned pmask = __ballot_sync(0xffffffffu, pres);
    int npres = __popc(pmask);
    float hv = pres ? g_hinge[b * CS + lane + 1] / safe : 0.f;
    float rg = pres ? sqrtf(ss) : 0.f;
    __syncwarp();

    float ph = 0.f, np = 0.f;
    if (pres) {
        for (int c2 = lane + 1; c2 < C; c2++) {
            if ((pmask >> c2) & 1u) {
                float pss = 0.f;
#pragma unroll
                for (int e = 0; e < E_; e++) {
                    float d = ce[e] - cents[b][c2][e];
                    pss = fmaf(d, d, pss);
                }
                float h = TWO_DDIST - sqrtf(pss);
                if (h > 0.f) ph += h * h;
                np += 1.f;
            }
        }
    }
    hv = wred(hv); rg = wred(rg); ph = wred(ph); np = wred(np);

    if (lane == 0) {
        float nv = (float)npres;
        part[b][0] = (npres > 0) ? hv / nv : 0.f;
        part[b][1] = (np > 0.f) ? ph / np : 0.f;
        part[b][2] = (npres > 0) ? rg / nv : 0.f;
        part[b][3] = (npres > 0) ? 1.f : 0.f;
    }
    __syncthreads();
    if (threadIdx.x == 0) {
        float sv = 0.f, sd = 0.f, sr = 0.f, vb = 0.f;
        for (int bb = 0; bb < B_; bb++) {
            sv += part[bb][0] * part[bb][3];
            sd += part[bb][1] * part[bb][3];
            sr += part[bb][2] * part[bb][3];
            vb += part[bb][3];
        }
        float den = fmaxf(vb, 1.f);
        float lv = (vb > 0.f) ? sv / den : 0.f;
        float ld = (vb > 0.f) ? sd / den : 0.f;
        float lr = (vb > 0.f) ? sr / den : 0.f;
        float tot = lv + ld + GAMMA_ * lr;
        out[0] = tot;
        if (out_size > 1) out[1] = lv;
        if (out_size > 2) out[2] = ld;
        if (out_size > 3) out[3] = lr;
    }
}

// ---------------- Pass 2: hinged variance + fused finalize ----------------
__global__ void __launch_bounds__(256) k_pass2(const float4* __restrict__ emb,
                                               const int4* __restrict__ mask,
                                               const int* __restrict__ ninst,
                                               float* __restrict__ out, int out_size) {
    __shared__ float csh[CS * 17];
    __shared__ float shinge[CS];
    __shared__ int is_last;
    int idx = blockIdx.x * blockDim.x + threadIdx.x;
    int b = idx >> N4SHIFT;   // constant per block

    if (threadIdx.x < CS) shinge[threadIdx.x] = 0.f;
    for (int i = threadIdx.x; i < CS * E_; i += blockDim.x) {
        int l = i >> 4, e = i & 15;
        csh[l * 17 + e] = g_sums[(b * CS + l) * E_ + e] / fmaxf(g_cnt[b * CS + l], 1.f);
    }
    __syncthreads();

    int n4 = idx & (N4_ - 1);
    int4 lab = mask[idx];
    const float4* ep = emb + (((size_t)b * E_) << N4SHIFT) + n4;

    const float* cx = &csh[lab.x * 17];
    const float* cy = &csh[lab.y * 17];
    const float* cz = &csh[lab.z * 17];
    const float* cw = &csh[lab.w * 17];

    float ssx = 0.f, ssy = 0.f, ssz = 0.f, ssw = 0.f;
#pragma unroll
    for (int e = 0; e < E_; e++) {
        float4 q = ep[(size_t)e << N4SHIFT];
        float dx = q.x - cx[e]; ssx = fmaf(dx, dx, ssx);
        float dy = q.y - cy[e]; ssy = fmaf(dy, dy, ssy);
        float dz = q.z - cz[e]; ssz = fmaf(dz, dz, ssz);
        float dw = q.w - cw[e]; ssw = fmaf(dw, dw, ssw);
    }
    if (lab.x > 0) { float h = sqrtf(ssx) - DVAR; if (h > 0.f) atomicAdd(&shinge[lab.x], h * h); }
    if (lab.y > 0) { float h = sqrtf(ssy) - DVAR; if (h > 0.f) atomicAdd(&shinge[lab.y], h * h); }
    if (lab.z > 0) { float h = sqrtf(ssz) - DVAR; if (h > 0.f) atomicAdd(&shinge[lab.z], h * h); }
    if (lab.w > 0) { float h = sqrtf(ssw) - DVAR; if (h > 0.f) atomicAdd(&shinge[lab.w], h * h); }
    __syncthreads();
    if (threadIdx.x < CS && shinge[threadIdx.x] != 0.f)
        red_add(&g_hinge[b * CS + threadIdx.x], shinge[threadIdx.x]);

    // last block runs finalize
    __syncthreads();
    if (threadIdx.x == 0) {
        __threadfence();
        unsigned v = atomicAdd(&g_done, 1u);
        is_last = (v == (unsigned)(GRID2 - 1));
    }
    __syncthreads();
    if (is_last) {
        __threadfence();
        do_finalize(ninst, out, out_size);
    }
}

extern "C" void kernel_launch(void* const* d_in, const int* in_sizes, int n_in,
                              void* d_out, int out_size) {
    const float* emb = (const float*)d_in[0];
    const int* mask = (const int*)d_in[1];
    const int* ninst = (const int*)d_in[2];
    (void)in_sizes; (void)n_in;

    cudaFuncSetAttribute(k_pass1, cudaFuncAttributeMaxDynamicSharedMemorySize, SMEM1_BYTES);

    k_zero<<<1, 512>>>();
    k_pass1<<<GRID1, T1, SMEM1_BYTES>>>(emb, mask);
    k_pass2<<<GRID2, 256>>>((const float4*)emb, (const int4*)mask,
                            ninst, (float*)d_out, out_size);
}

// round 8
// speedup vs baseline: 1.5062x; 1.0458x over previous
#include <cuda_runtime.h>

// DiscriminativeLoss: B=8, E=16, N=512*512, C<=32
// R7: pass1 staging via cp.async.bulk + mbarrier (kills LDGSTS issue cost);
// k_zero removed (globals self-cleaned by finalize block each run).
// K1 pass1 (sorted segment sums) -> K2 pass2 (+fused finalize+cleanup).

namespace {
constexpr int B_ = 8;
constexpr int E_ = 16;
constexpr int NSHIFT = 18;        // N = 2^18 pixels per batch
constexpr int N_ = 1 << NSHIFT;
constexpr int N4_ = N_ / 4;
constexpr int N4SHIFT = 16;
constexpr int CMAX = 32;
constexpr int CS = 33;            // labels 0..32 (0 = background)
constexpr float DVAR = 0.5f;
constexpr float TWO_DDIST = 3.0f;
constexpr float GAMMA_ = 0.001f;

// pass1 tiling
constexpr int TPX = 1024;                    // pixels per tile
constexpr int T1 = 512;                      // pass1 threads (2 px/thread)
constexpr int TILES_PER_B = N_ / TPX;        // 256
constexpr int BPB = 18;                      // blocks per batch
constexpr int GRID1 = B_ * BPB;              // 144
// chunking: first 4 blocks/batch take 15 tiles, rest 14 (4*15+14*14=256)
// dynamic smem layout (float indices)
constexpr int EMB_BUF_F = E_ * TPX;          // 16384 per buffer (contiguous rows)
constexpr int LAB_OFF_F = 2 * EMB_BUF_F;     // 32768
constexpr int SORT_OFF_F = LAB_OFF_F + 2 * TPX;   // 34816
constexpr int HIST_OFF_F = SORT_OFF_F + TPX / 2;  // 35328
constexpr int MBAR_OFF_F = HIST_OFF_F + 132;      // 35460 (8B aligned)
constexpr int SMEM1_FLOATS = MBAR_OFF_F + 4;
constexpr int SMEM1_BYTES = SMEM1_FLOATS * 4;     // ~138.5 KB
constexpr unsigned TILE_TX = (TPX * E_ + TPX) * 4; // 69632 bytes per tile

constexpr int GRID2 = B_ * N4_ / 256;        // 2048
}

__device__ __align__(16) float g_sums[B_ * CS * E_];
__device__ float g_cnt[B_ * CS];
__device__ float g_hinge[B_ * CS];
__device__ unsigned g_done;

__device__ __forceinline__ void red_add_v4(float* a, float x, float y, float z, float w) {
    asm volatile("red.global.add.v4.f32 [%0], {%1,%2,%3,%4};"
                 :: "l"(a), "f"(x), "f"(y), "f"(z), "f"(w) : "memory");
}
__device__ __forceinline__ void red_add(float* a, float v) {
    asm volatile("red.global.add.f32 [%0], %1;" :: "l"(a), "f"(v) : "memory");
}
__device__ __forceinline__ unsigned smem_u32(const void* p) {
    unsigned a;
    asm("{ .reg .u64 t; cvta.to.shared.u64 t, %1; cvt.u32.u64 %0, t; }" : "=r"(a) : "l"(p));
    return a;
}
__device__ __forceinline__ void bulk_cp(unsigned dst, const void* src, unsigned bytes, unsigned mbar) {
    asm volatile("cp.async.bulk.shared::cta.global.mbarrier::complete_tx::bytes [%0], [%1], %2, [%3];"
                 :: "r"(dst), "l"(src), "r"(bytes), "r"(mbar) : "memory");
}
__device__ __forceinline__ void mbar_init(unsigned mbar, unsigned cnt) {
    asm volatile("mbarrier.init.shared.b64 [%0], %1;" :: "r"(mbar), "r"(cnt) : "memory");
}
__device__ __forceinline__ void mbar_expect_tx(unsigned mbar, unsigned bytes) {
    asm volatile("mbarrier.arrive.expect_tx.shared.b64 _, [%0], %1;" :: "r"(mbar), "r"(bytes) : "memory");
}
__device__ __forceinline__ void mbar_wait(unsigned mbar, unsigned parity) {
    asm volatile(
        "{\n\t"
        ".reg .pred P1;\n\t"
        "WAIT_LOOP_%=:\n\t"
        "mbarrier.try_wait.parity.acquire.cta.shared::cta.b64 P1, [%0], %1, 0x989680;\n\t"
        "@P1 bra.uni WAIT_DONE_%=;\n\t"
        "bra.uni WAIT_LOOP_%=;\n\t"
        "WAIT_DONE_%=:\n\t"
        "}"
        :: "r"(mbar), "r"(parity) : "memory");
}
__device__ __forceinline__ float wred(float v) {
#pragma unroll
    for (int o = 16; o; o >>= 1) v += __shfl_xor_sync(0xffffffffu, v, o);
    return v;
}

// ---------------- Pass 1: sorted segment sums, bulk-copy staged ----------------
__global__ void __launch_bounds__(T1) k_pass1(const float* __restrict__ emb,
                                              const int* __restrict__ mask) {
    extern __shared__ float sm[];
    int* labS = (int*)(sm + LAB_OFF_F);
    unsigned short* sortedS = (unsigned short*)(sm + SORT_OFF_F);
    int* shist = (int*)(sm + HIST_OFF_F);
    int* soff = shist + CS;
    int* scur = soff + CS;
    int* ctot = scur + CS;

    const int tid = threadIdx.x;
    const int lane = tid & 31;
    const int wid = tid >> 5;
    const unsigned smem_base = smem_u32(sm);
    const unsigned mbar0 = smem_base + MBAR_OFF_F * 4u;
    const unsigned mbar1 = mbar0 + 8u;

    const int b = blockIdx.x / BPB;
    const int chunk = blockIdx.x % BPB;
    const int nt = 14 + (chunk < 4 ? 1 : 0);
    const int tstart = chunk * 14 + (chunk < 4 ? chunk : 4);

    if (tid == 0) { mbar_init(mbar0, 1); mbar_init(mbar1, 1); }
    if (wid == 0) ctot[lane] = 0;
    __syncthreads();

    auto prefetch = [&](int tt, int buf) {
        if (tid != 0) return;
        unsigned mb = buf ? mbar1 : mbar0;
        asm volatile("fence.proxy.async.shared::cta;" ::: "memory");
        mbar_expect_tx(mb, TILE_TX);
        int gp0 = tt << 10;
        const float* ebase = emb + (((size_t)b * E_) << NSHIFT) + gp0;
        unsigned dbase = smem_base + (unsigned)(buf * EMB_BUF_F) * 4u;
#pragma unroll
        for (int e = 0; e < E_; e++)
            bulk_cp(dbase + (unsigned)(e * TPX) * 4u,
                    ebase + ((size_t)e << NSHIFT), TPX * 4u, mb);
        bulk_cp(smem_base + (unsigned)(LAB_OFF_F + buf * TPX) * 4u,
                mask + ((size_t)b << NSHIFT) + gp0, TPX * 4u, mb);
    };

    float acc0[E_], acc1[E_];
#pragma unroll
    for (int e = 0; e < E_; e++) { acc0[e] = 0.f; acc1[e] = 0.f; }
    const int la = 2 * wid + 1;                   // labels owned by this warp
    const int lb = 2 * wid + 2;

    prefetch(tstart, 0);
    unsigned ph0 = 0, ph1 = 0;

    for (int k = 0; k < nt; k++) {
        int buf = k & 1;
        if (k + 1 < nt) prefetch(tstart + k + 1, buf ^ 1);

        if (tid < CS) shist[tid] = 0;
        if (buf == 0) { mbar_wait(mbar0, ph0); ph0 ^= 1u; }
        else          { mbar_wait(mbar1, ph1); ph1 ^= 1u; }
        __syncthreads();

        const float* eb = sm + buf * EMB_BUF_F;
        int l0 = labS[buf * TPX + tid];
        int l1 = labS[buf * TPX + tid + T1];

        // histogram: one aggregated ATOMS per distinct label per warp
        unsigned m0 = __match_any_sync(0xffffffffu, l0);
        int lead0 = __ffs(m0) - 1, cnt0 = __popc(m0), rk0 = __popc(m0 & ((1u << lane) - 1u));
        if (l0 > 0 && lane == lead0) atomicAdd(&shist[l0], cnt0);
        unsigned m1 = __match_any_sync(0xffffffffu, l1);
        int lead1 = __ffs(m1) - 1, cnt1 = __popc(m1), rk1 = __popc(m1 & ((1u << lane) - 1u));
        if (l1 > 0 && lane == lead1) atomicAdd(&shist[l1], cnt1);
        __syncthreads();

        // scan (warp 0: labels 1..32 on lanes 0..31) + count accumulation
        if (wid == 0) {
            int c = shist[lane + 1];
            ctot[lane] += c;
            int inc = c;
#pragma unroll
            for (int o = 1; o < 32; o <<= 1) {
                int v = __shfl_up_sync(0xffffffffu, inc, o);
                if (lane >= o) inc += v;
            }
            int start = inc - c;
            soff[lane + 1] = start;
            scur[lane + 1] = start;
        }
        __syncthreads();

        // scatter (warp-aggregated)
        int base0 = 0;
        if (l0 > 0 && lane == lead0) base0 = atomicAdd(&scur[l0], cnt0);
        base0 = __shfl_sync(0xffffffffu, base0, lead0);
        if (l0 > 0) sortedS[base0 + rk0] = (unsigned short)tid;
        int base1 = 0;
        if (l1 > 0 && lane == lead1) base1 = atomicAdd(&scur[l1], cnt1);
        base1 = __shfl_sync(0xffffffffu, base1, lead1);
        if (l1 > 0) sortedS[base1 + rk1] = (unsigned short)(tid + T1);
        __syncthreads();

        // gather into persistent per-lane accumulators
        {
            int m = shist[la], st = soff[la];
            for (int p = lane; p < m; p += 32) {
                const float* px = eb + sortedS[st + p];
#pragma unroll
                for (int e = 0; e < E_; e++) acc0[e] += px[e * TPX];
            }
        }
        {
            int m = shist[lb], st = soff[lb];
            for (int p = lane; p < m; p += 32) {
                const float* px = eb + sortedS[st + p];
#pragma unroll
                for (int e = 0; e < E_; e++) acc1[e] += px[e * TPX];
            }
        }
        __syncthreads();   // protect sort arrays + buffers for reuse
    }

    // one reduction + emission per block
#pragma unroll
    for (int o = 16; o; o >>= 1) {
#pragma unroll
        for (int e = 0; e < E_; e++) {
            acc0[e] += __shfl_xor_sync(0xffffffffu, acc0[e], o);
            acc1[e] += __shfl_xor_sync(0xffffffffu, acc1[e], o);
        }
    }
    if (lane == 0) {
        float* d0 = &g_sums[(b * CS + la) * E_];
        red_add_v4(d0 + 0, acc0[0], acc0[1], acc0[2], acc0[3]);
        red_add_v4(d0 + 4, acc0[4], acc0[5], acc0[6], acc0[7]);
        red_add_v4(d0 + 8, acc0[8], acc0[9], acc0[10], acc0[11]);
        red_add_v4(d0 + 12, acc0[12], acc0[13], acc0[14], acc0[15]);
        float* d1 = &g_sums[(b * CS + lb) * E_];
        red_add_v4(d1 + 0, acc1[0], acc1[1], acc1[2], acc1[3]);
        red_add_v4(d1 + 4, acc1[4], acc1[5], acc1[6], acc1[7]);
        red_add_v4(d1 + 8, acc1[8], acc1[9], acc1[10], acc1[11]);
        red_add_v4(d1 + 12, acc1[12], acc1[13], acc1[14], acc1[15]);
    }
    if (wid == 0 && ctot[lane] > 0)
        red_add(&g_cnt[b * CS + lane + 1], (float)ctot[lane]);
}

// ---------------- finalize (runs in last pass2 block) ----------------
__device__ void do_finalize(const int* __restrict__ ninst,
                            float* __restrict__ out, int out_size) {
    __shared__ float cents[B_][CMAX][E_ + 1];
    __shared__ float part[B_][4];
    int C = *ninst; if (C > CMAX) C = CMAX;
    int lane = threadIdx.x & 31;
    int b = threadIdx.x >> 5;

    float cnt = (lane < C) ? g_cnt[b * CS + lane + 1] : 0.f;
    bool pres = cnt > 0.f;
    float safe = fmaxf(cnt, 1.f);

    float ce[E_];
    float ss = 0.f;
#pragma unroll
    for (int e = 0; e < E_; e++) {
        float v = (lane < C) ? g_sums[(b * CS + lane + 1) * E_ + e] / safe : 0.f;
        ce[e] = v;
        cents[b][lane][e] = v;
        ss = fmaf(v, v, ss);
    }
    unsigned pmask = __ballot_sync(0xffffffffu, pres);
    int npres = __popc(pmask);
    float hv = pres ? g_hinge[b * CS + lane + 1] / safe : 0.f;
    float rg = pres ? sqrtf(ss) : 0.f;
    __syncwarp();

    float ph = 0.f, np = 0.f;
    if (pres) {
        for (int c2 = lane + 1; c2 < C; c2++) {
            if ((pmask >> c2) & 1u) {
                float pss = 0.f;
#pragma unroll
                for (int e = 0; e < E_; e++) {
                    float d = ce[e] - cents[b][c2][e];
                    pss = fmaf(d, d, pss);
                }
                float h = TWO_DDIST - sqrtf(pss);
                if (h > 0.f) ph += h * h;
                np += 1.f;
            }
        }
    }
    hv = wred(hv); rg = wred(rg); ph = wred(ph); np = wred(np);

    if (lane == 0) {
        float nv = (float)npres;
        part[b][0] = (npres > 0) ? hv / nv : 0.f;
        part[b][1] = (np > 0.f) ? ph / np : 0.f;
        part[b][2] = (npres > 0) ? rg / nv : 0.f;
        part[b][3] = (npres > 0) ? 1.f : 0.f;
    }
    __syncthreads();
    if (threadIdx.x == 0) {
        float sv = 0.f, sd = 0.f, sr = 0.f, vb = 0.f;
        for (int bb = 0; bb < B_; bb++) {
            sv += part[bb][0] * part[bb][3];
            sd += part[bb][1] * part[bb][3];
            sr += part[bb][2] * part[bb][3];
            vb += part[bb][3];
        }
        float den = fmaxf(vb, 1.f);
        float lv = (vb > 0.f) ? sv / den : 0.f;
        float ld = (vb > 0.f) ? sd / den : 0.f;
        float lr = (vb > 0.f) ? sr / den : 0.f;
        float tot = lv + ld + GAMMA_ * lr;
        out[0] = tot;
        if (out_size > 1) out[1] = lv;
        if (out_size > 2) out[2] = ld;
        if (out_size > 3) out[3] = lr;
    }
}

// ---------------- Pass 2: hinged variance + fused finalize + cleanup ----------------
__global__ void __launch_bounds__(256) k_pass2(const float4* __restrict__ emb,
                                               const int4* __restrict__ mask,
                                               const int* __restrict__ ninst,
                                               float* __restrict__ out, int out_size) {
    __shared__ float csh[CS * 17];
    __shared__ float shinge[CS];
    __shared__ int is_last;
    int idx = blockIdx.x * blockDim.x + threadIdx.x;
    int b = idx >> N4SHIFT;   // constant per block

    if (threadIdx.x < CS) shinge[threadIdx.x] = 0.f;
    for (int i = threadIdx.x; i < CS * E_; i += blockDim.x) {
        int l = i >> 4, e = i & 15;
        csh[l * 17 + e] = g_sums[(b * CS + l) * E_ + e] / fmaxf(g_cnt[b * CS + l], 1.f);
    }
    __syncthreads();

    int n4 = idx & (N4_ - 1);
    int4 lab = mask[idx];
    const float4* ep = emb + (((size_t)b * E_) << N4SHIFT) + n4;

    const float* cx = &csh[lab.x * 17];
    const float* cy = &csh[lab.y * 17];
    const float* cz = &csh[lab.z * 17];
    const float* cw = &csh[lab.w * 17];

    float ssx = 0.f, ssy = 0.f, ssz = 0.f, ssw = 0.f;
#pragma unroll
    for (int e = 0; e < E_; e++) {
        float4 q = ep[(size_t)e << N4SHIFT];
        float dx = q.x - cx[e]; ssx = fmaf(dx, dx, ssx);
        float dy = q.y - cy[e]; ssy = fmaf(dy, dy, ssy);
        float dz = q.z - cz[e]; ssz = fmaf(dz, dz, ssz);
        float dw = q.w - cw[e]; ssw = fmaf(dw, dw, ssw);
    }
    if (lab.x > 0) { float h = sqrtf(ssx) - DVAR; if (h > 0.f) atomicAdd(&shinge[lab.x], h * h); }
    if (lab.y > 0) { float h = sqrtf(ssy) - DVAR; if (h > 0.f) atomicAdd(&shinge[lab.y], h * h); }
    if (lab.z > 0) { float h = sqrtf(ssz) - DVAR; if (h > 0.f) atomicAdd(&shinge[lab.z], h * h); }
    if (lab.w > 0) { float h = sqrtf(ssw) - DVAR; if (h > 0.f) atomicAdd(&shinge[lab.w], h * h); }
    __syncthreads();
    if (threadIdx.x < CS && shinge[threadIdx.x] != 0.f)
        red_add(&g_hinge[b * CS + threadIdx.x], shinge[threadIdx.x]);

    // last block runs finalize, then self-cleans global state for next replay
    __syncthreads();
    if (threadIdx.x == 0) {
        __threadfence();
        unsigned v = atomicAdd(&g_done, 1u);
        is_last = (v == (unsigned)(GRID2 - 1));
    }
    __syncthreads();
    if (is_last) {
        __threadfence();
        do_finalize(ninst, out, out_size);
        __syncthreads();
        for (int i = threadIdx.x; i < B_ * CS * E_; i += blockDim.x) g_sums[i] = 0.f;
        for (int i = threadIdx.x; i < B_ * CS; i += blockDim.x) { g_cnt[i] = 0.f; g_hinge[i] = 0.f; }
        if (threadIdx.x == 0) g_done = 0u;
    }
}

extern "C" void kernel_launch(void* const* d_in, const int* in_sizes, int n_in,
                              void* d_out, int out_size) {
    const float* emb = (const float*)d_in[0];
    const int* mask = (const int*)d_in[1];
    const int* ninst = (const int*)d_in[2];
    (void)in_sizes; (void)n_in;

    cudaFuncSetAttribute(k_pass1, cudaFuncAttributeMaxDynamicSharedMemorySize, SMEM1_BYTES);

    k_pass1<<<GRID1, T1, SMEM1_BYTES>>>(emb, mask);
    k_pass2<<<GRID2, 256>>>((const float4*)emb, (const int4*)mask,
                            ninst, (float*)d_out, out_size);
}

// round 9
// speedup vs baseline: 1.6159x; 1.0728x over previous
#include <cuda_runtime.h>

// DiscriminativeLoss: B=8, E=16, N=512*512, C<=32
// R8: pass1 triple-buffered TMA staging; finalize distributed (per-batch
// pairwise/reg terms computed by designated pass2 blocks; last block only
// folds hinge + combines).
// K1 pass1 (sorted segment sums) -> K2 pass2 (+distributed finalize+cleanup).

namespace {
constexpr int B_ = 8;
constexpr int E_ = 16;
constexpr int NSHIFT = 18;        // N = 2^18 pixels per batch
constexpr int N_ = 1 << NSHIFT;
constexpr int N4_ = N_ / 4;
constexpr int N4SHIFT = 16;
constexpr int CMAX = 32;
constexpr int CS = 33;            // labels 0..32 (0 = background)
constexpr float DVAR = 0.5f;
constexpr float TWO_DDIST = 3.0f;
constexpr float GAMMA_ = 0.001f;

// pass1 tiling
constexpr int TPX = 1024;                    // pixels per tile
constexpr int T1 = 512;                      // pass1 threads (2 px/thread)
constexpr int TILES_PER_B = N_ / TPX;        // 256
constexpr int BPB = 18;                      // blocks per batch
constexpr int GRID1 = B_ * BPB;              // 144
// chunking: first 4 blocks/batch take 15 tiles, rest 14 (4*15+14*14=256)
// dynamic smem layout (float indices), 3-deep pipeline
constexpr int NBUF = 3;
constexpr int EMB_BUF_F = E_ * TPX;               // 16384 per buffer
constexpr int LAB_OFF_F = NBUF * EMB_BUF_F;       // 49152
constexpr int SORT_OFF_F = LAB_OFF_F + NBUF * TPX;  // 52224
constexpr int HIST_OFF_F = SORT_OFF_F + TPX / 2;    // 52736
constexpr int MBAR_OFF_F = HIST_OFF_F + 132;        // 52868 (8B aligned *4)
constexpr int SMEM1_FLOATS = MBAR_OFF_F + 8;
constexpr int SMEM1_BYTES = SMEM1_FLOATS * 4;       // ~211.5 KB
constexpr unsigned TILE_TX = (TPX * E_ + TPX) * 4;  // 69632 bytes per tile

constexpr int GRID2 = B_ * N4_ / 256;        // 2048
}

__device__ __align__(16) float g_sums[B_ * CS * E_];
__device__ float g_cnt[B_ * CS];
__device__ float g_hinge[B_ * CS];
__device__ float g_part[B_ * 4];   // per-batch: {loss_dist_b, reg_sum, npres}
__device__ unsigned g_done;

__device__ __forceinline__ void red_add_v4(float* a, float x, float y, float z, float w) {
    asm volatile("red.global.add.v4.f32 [%0], {%1,%2,%3,%4};"
                 :: "l"(a), "f"(x), "f"(y), "f"(z), "f"(w) : "memory");
}
__device__ __forceinline__ void red_add(float* a, float v) {
    asm volatile("red.global.add.f32 [%0], %1;" :: "l"(a), "f"(v) : "memory");
}
__device__ __forceinline__ unsigned smem_u32(const void* p) {
    unsigned a;
    asm("{ .reg .u64 t; cvta.to.shared.u64 t, %1; cvt.u32.u64 %0, t; }" : "=r"(a) : "l"(p));
    return a;
}
__device__ __forceinline__ void bulk_cp(unsigned dst, const void* src, unsigned bytes, unsigned mbar) {
    asm volatile("cp.async.bulk.shared::cta.global.mbarrier::complete_tx::bytes [%0], [%1], %2, [%3];"
                 :: "r"(dst), "l"(src), "r"(bytes), "r"(mbar) : "memory");
}
__device__ __forceinline__ void mbar_init(unsigned mbar, unsigned cnt) {
    asm volatile("mbarrier.init.shared.b64 [%0], %1;" :: "r"(mbar), "r"(cnt) : "memory");
}
__device__ __forceinline__ void mbar_expect_tx(unsigned mbar, unsigned bytes) {
    asm volatile("mbarrier.arrive.expect_tx.shared.b64 _, [%0], %1;" :: "r"(mbar), "r"(bytes) : "memory");
}
__device__ __forceinline__ void mbar_wait(unsigned mbar, unsigned parity) {
    asm volatile(
        "{\n\t"
        ".reg .pred P1;\n\t"
        "WAIT_LOOP_%=:\n\t"
        "mbarrier.try_wait.parity.acquire.cta.shared::cta.b64 P1, [%0], %1, 0x989680;\n\t"
        "@P1 bra.uni WAIT_DONE_%=;\n\t"
        "bra.uni WAIT_LOOP_%=;\n\t"
        "WAIT_DONE_%=:\n\t"
        "}"
        :: "r"(mbar), "r"(parity) : "memory");
}
__device__ __forceinline__ float wred(float v) {
#pragma unroll
    for (int o = 16; o; o >>= 1) v += __shfl_xor_sync(0xffffffffu, v, o);
    return v;
}

// ---------------- Pass 1: sorted segment sums, 3-deep bulk-copy pipeline ----------------
__global__ void __launch_bounds__(T1) k_pass1(const float* __restrict__ emb,
                                              const int* __restrict__ mask) {
    extern __shared__ float sm[];
    int* labS = (int*)(sm + LAB_OFF_F);
    unsigned short* sortedS = (unsigned short*)(sm + SORT_OFF_F);
    int* shist = (int*)(sm + HIST_OFF_F);
    int* soff = shist + CS;
    int* scur = soff + CS;
    int* ctot = scur + CS;

    const int tid = threadIdx.x;
    const int lane = tid & 31;
    const int wid = tid >> 5;
    const unsigned smem_base = smem_u32(sm);
    const unsigned mbarB = smem_base + MBAR_OFF_F * 4u;

    const int b = blockIdx.x / BPB;
    const int chunk = blockIdx.x % BPB;
    const int nt = 14 + (chunk < 4 ? 1 : 0);
    const int tstart = chunk * 14 + (chunk < 4 ? chunk : 4);

    if (tid == 0) {
#pragma unroll
        for (int i = 0; i < NBUF; i++) mbar_init(mbarB + i * 8u, 1);
    }
    if (wid == 0) ctot[lane] = 0;
    __syncthreads();

    auto prefetch = [&](int tt, int buf) {
        if (tid != 0) return;
        unsigned mb = mbarB + (unsigned)buf * 8u;
        asm volatile("fence.proxy.async.shared::cta;" ::: "memory");
        mbar_expect_tx(mb, TILE_TX);
        int gp0 = tt << 10;
        const float* ebase = emb + (((size_t)b * E_) << NSHIFT) + gp0;
        unsigned dbase = smem_base + (unsigned)(buf * EMB_BUF_F) * 4u;
#pragma unroll
        for (int e = 0; e < E_; e++)
            bulk_cp(dbase + (unsigned)(e * TPX) * 4u,
                    ebase + ((size_t)e << NSHIFT), TPX * 4u, mb);
        bulk_cp(smem_base + (unsigned)(LAB_OFF_F + buf * TPX) * 4u,
                mask + ((size_t)b << NSHIFT) + gp0, TPX * 4u, mb);
    };

    float acc0[E_], acc1[E_];
#pragma unroll
    for (int e = 0; e < E_; e++) { acc0[e] = 0.f; acc1[e] = 0.f; }
    const int la = 2 * wid + 1;                   // labels owned by this warp
    const int lb = 2 * wid + 2;

    prefetch(tstart, 0);
    if (nt > 1) prefetch(tstart + 1, 1);

    for (int k = 0; k < nt; k++) {
        int buf = k % NBUF;
        if (k + 2 < nt) prefetch(tstart + k + 2, (k + 2) % NBUF);

        if (tid < CS) shist[tid] = 0;
        mbar_wait(mbarB + (unsigned)buf * 8u, (unsigned)((k / NBUF) & 1));
        __syncthreads();

        const float* eb = sm + buf * EMB_BUF_F;
        int l0 = labS[buf * TPX + tid];
        int l1 = labS[buf * TPX + tid + T1];

        // histogram: one aggregated ATOMS per distinct label per warp
        unsigned m0 = __match_any_sync(0xffffffffu, l0);
        int lead0 = __ffs(m0) - 1, cnt0 = __popc(m0), rk0 = __popc(m0 & ((1u << lane) - 1u));
        if (l0 > 0 && lane == lead0) atomicAdd(&shist[l0], cnt0);
        unsigned m1 = __match_any_sync(0xffffffffu, l1);
        int lead1 = __ffs(m1) - 1, cnt1 = __popc(m1), rk1 = __popc(m1 & ((1u << lane) - 1u));
        if (l1 > 0 && lane == lead1) atomicAdd(&shist[l1], cnt1);
        __syncthreads();

        // scan (warp 0: labels 1..32 on lanes 0..31) + count accumulation
        if (wid == 0) {
            int c = shist[lane + 1];
            ctot[lane] += c;
            int inc = c;
#pragma unroll
            for (int o = 1; o < 32; o <<= 1) {
                int v = __shfl_up_sync(0xffffffffu, inc, o);
                if (lane >= o) inc += v;
            }
            int start = inc - c;
            soff[lane + 1] = start;
            scur[lane + 1] = start;
        }
        __syncthreads();

        // scatter (warp-aggregated)
        int base0 = 0;
        if (l0 > 0 && lane == lead0) base0 = atomicAdd(&scur[l0], cnt0);
        base0 = __shfl_sync(0xffffffffu, base0, lead0);
        if (l0 > 0) sortedS[base0 + rk0] = (unsigned short)tid;
        int base1 = 0;
        if (l1 > 0 && lane == lead1) base1 = atomicAdd(&scur[l1], cnt1);
        base1 = __shfl_sync(0xffffffffu, base1, lead1);
        if (l1 > 0) sortedS[base1 + rk1] = (unsigned short)(tid + T1);
        __syncthreads();

        // gather into persistent per-lane accumulators
        {
            int m = shist[la], st = soff[la];
            for (int p = lane; p < m; p += 32) {
                const float* px = eb + sortedS[st + p];
#pragma unroll
                for (int e = 0; e < E_; e++) acc0[e] += px[e * TPX];
            }
        }
        {
            int m = shist[lb], st = soff[lb];
            for (int p = lane; p < m; p += 32) {
                const float* px = eb + sortedS[st + p];
#pragma unroll
                for (int e = 0; e < E_; e++) acc1[e] += px[e * TPX];
            }
        }
        __syncthreads();   // protect sort arrays + buffers for reuse
    }

    // one reduction + emission per block
#pragma unroll
    for (int o = 16; o; o >>= 1) {
#pragma unroll
        for (int e = 0; e < E_; e++) {
            acc0[e] += __shfl_xor_sync(0xffffffffu, acc0[e], o);
            acc1[e] += __shfl_xor_sync(0xffffffffu, acc1[e], o);
        }
    }
    if (lane == 0) {
        float* d0 = &g_sums[(b * CS + la) * E_];
        red_add_v4(d0 + 0, acc0[0], acc0[1], acc0[2], acc0[3]);
        red_add_v4(d0 + 4, acc0[4], acc0[5], acc0[6], acc0[7]);
        red_add_v4(d0 + 8, acc0[8], acc0[9], acc0[10], acc0[11]);
        red_add_v4(d0 + 12, acc0[12], acc0[13], acc0[14], acc0[15]);
        float* d1 = &g_sums[(b * CS + lb) * E_];
        red_add_v4(d1 + 0, acc1[0], acc1[1], acc1[2], acc1[3]);
        red_add_v4(d1 + 4, acc1[4], acc1[5], acc1[6], acc1[7]);
        red_add_v4(d1 + 8, acc1[8], acc1[9], acc1[10], acc1[11]);
        red_add_v4(d1 + 12, acc1[12], acc1[13], acc1[14], acc1[15]);
    }
    if (wid == 0 && ctot[lane] > 0)
        red_add(&g_cnt[b * CS + lane + 1], (float)ctot[lane]);
}

// ---------------- Pass 2: hinged variance + distributed finalize ----------------
__global__ void __launch_bounds__(256) k_pass2(const float4* __restrict__ emb,
                                               const int4* __restrict__ mask,
                                               const int* __restrict__ ninst,
                                               float* __restrict__ out, int out_size) {
    __shared__ float csh[CS * 17];
    __shared__ float shinge[CS];
    __shared__ int is_last;
    int idx = blockIdx.x * blockDim.x + threadIdx.x;
    int b = idx >> N4SHIFT;   // constant per block

    if (threadIdx.x < CS) shinge[threadIdx.x] = 0.f;
    for (int i = threadIdx.x; i < CS * E_; i += blockDim.x) {
        int l = i >> 4, e = i & 15;
        csh[l * 17 + e] = g_sums[(b * CS + l) * E_ + e] / fmaxf(g_cnt[b * CS + l], 1.f);
    }
    __syncthreads();

    int n4 = idx & (N4_ - 1);
    int4 lab = mask[idx];
    const float4* ep = emb + (((size_t)b * E_) << N4SHIFT) + n4;

    const float* cx = &csh[lab.x * 17];
    const float* cy = &csh[lab.y * 17];
    const float* cz = &csh[lab.z * 17];
    const float* cw = &csh[lab.w * 17];

    float ssx = 0.f, ssy = 0.f, ssz = 0.f, ssw = 0.f;
#pragma unroll
    for (int e = 0; e < E_; e++) {
        float4 q = ep[(size_t)e << N4SHIFT];
        float dx = q.x - cx[e]; ssx = fmaf(dx, dx, ssx);
        float dy = q.y - cy[e]; ssy = fmaf(dy, dy, ssy);
        float dz = q.z - cz[e]; ssz = fmaf(dz, dz, ssz);
        float dw = q.w - cw[e]; ssw = fmaf(dw, dw, ssw);
    }
    if (lab.x > 0) { float h = sqrtf(ssx) - DVAR; if (h > 0.f) atomicAdd(&shinge[lab.x], h * h); }
    if (lab.y > 0) { float h = sqrtf(ssy) - DVAR; if (h > 0.f) atomicAdd(&shinge[lab.y], h * h); }
    if (lab.z > 0) { float h = sqrtf(ssz) - DVAR; if (h > 0.f) atomicAdd(&shinge[lab.z], h * h); }
    if (lab.w > 0) { float h = sqrtf(ssw) - DVAR; if (h > 0.f) atomicAdd(&shinge[lab.w], h * h); }
    __syncthreads();
    if (threadIdx.x < CS && shinge[threadIdx.x] != 0.f)
        red_add(&g_hinge[b * CS + threadIdx.x], shinge[threadIdx.x]);

    // designated block per batch computes pairwise-dist + reg terms (pass1-only deps)
    if ((blockIdx.x & 255) == 0) {
        __shared__ float sph, snp;
        __shared__ unsigned spmask;
        __shared__ int sC;
        if (threadIdx.x == 0) {
            sph = 0.f; snp = 0.f;
            int Cv = *ninst; if (Cv > CMAX) Cv = CMAX;
            sC = Cv;
        }
        __syncthreads();
        int C = sC;
        if (threadIdx.x < 32) {
            float cnt = (threadIdx.x < C) ? g_cnt[b * CS + threadIdx.x + 1] : 0.f;
            unsigned pm0 = __ballot_sync(0xffffffffu, cnt > 0.f);
            if (threadIdx.x == 0) spmask = pm0;
        }
        __syncthreads();
        unsigned pm = spmask;
        float ph = 0.f, np = 0.f;
        for (int q = threadIdx.x; q < 1024; q += 256) {
            int c1 = q >> 5, c2 = q & 31;
            if (c2 > c1 && ((pm >> c1) & 1u) && ((pm >> c2) & 1u)) {
                float pss = 0.f;
#pragma unroll
                for (int e = 0; e < E_; e++) {
                    float d = csh[(c1 + 1) * 17 + e] - csh[(c2 + 1) * 17 + e];
                    pss = fmaf(d, d, pss);
                }
                float h = TWO_DDIST - sqrtf(pss);
                if (h > 0.f) ph += h * h;
                np += 1.f;
            }
        }
        ph = wred(ph); np = wred(np);
        if ((threadIdx.x & 31) == 0) { atomicAdd(&sph, ph); atomicAdd(&snp, np); }
        float rg = 0.f;
        if (threadIdx.x < 32) {
            if ((pm >> threadIdx.x) & 1u) {
                float ss = 0.f;
#pragma unroll
                for (int e = 0; e < E_; e++) {
                    float v = csh[(threadIdx.x + 1) * 17 + e];
                    ss = fmaf(v, v, ss);
                }
                rg = sqrtf(ss);
            }
            rg = wred(rg);
        }
        __syncthreads();
        if (threadIdx.x == 0) {
            g_part[b * 4 + 0] = (snp > 0.f) ? sph / snp : 0.f;   // loss_dist_b
            g_part[b * 4 + 1] = rg;                              // sum of center norms
            g_part[b * 4 + 2] = (float)__popc(pm);               // n_present
        }
    }

    // last block: fold hinge + combine (tiny)
    __syncthreads();
    if (threadIdx.x == 0) {
        __threadfence();
        unsigned v = atomicAdd(&g_done, 1u);
        is_last = (v == (unsigned)(GRID2 - 1));
    }
    __syncthreads();
    if (is_last) {
        __threadfence();
        __shared__ float fpart[B_][4];
        int C = *ninst; if (C > CMAX) C = CMAX;
        int lane = threadIdx.x & 31;
        int bb = threadIdx.x >> 5;
        float cnt = (lane < C) ? g_cnt[bb * CS + lane + 1] : 0.f;
        bool pres = cnt > 0.f;
        float hv = pres ? g_hinge[bb * CS + lane + 1] / fmaxf(cnt, 1.f) : 0.f;
        hv = wred(hv);
        if (lane == 0) {
            float npres = g_part[bb * 4 + 2];
            float valid = (npres > 0.f) ? 1.f : 0.f;
            fpart[bb][0] = (npres > 0.f) ? hv / npres : 0.f;
            fpart[bb][1] = g_part[bb * 4 + 0];
            fpart[bb][2] = (npres > 0.f) ? g_part[bb * 4 + 1] / npres : 0.f;
            fpart[bb][3] = valid;
        }
        __syncthreads();
        if (threadIdx.x == 0) {
            float sv = 0.f, sd = 0.f, sr = 0.f, vb = 0.f;
            for (int i = 0; i < B_; i++) {
                sv += fpart[i][0] * fpart[i][3];
                sd += fpart[i][1] * fpart[i][3];
                sr += fpart[i][2] * fpart[i][3];
                vb += fpart[i][3];
            }
            float den = fmaxf(vb, 1.f);
            float lv = (vb > 0.f) ? sv / den : 0.f;
            float ld = (vb > 0.f) ? sd / den : 0.f;
            float lr = (vb > 0.f) ? sr / den : 0.f;
            out[0] = lv + ld + GAMMA_ * lr;
            if (out_size > 1) out[1] = lv;
            if (out_size > 2) out[2] = ld;
            if (out_size > 3) out[3] = lr;
        }
        // self-clean for next graph replay
        __syncthreads();
        for (int i = threadIdx.x; i < B_ * CS * E_; i += blockDim.x) g_sums[i] = 0.f;
        for (int i = threadIdx.x; i < B_ * CS; i += blockDim.x) { g_cnt[i] = 0.f; g_hinge[i] = 0.f; }
        if (threadIdx.x == 0) g_done = 0u;
    }
}

extern "C" void kernel_launch(void* const* d_in, const int* in_sizes, int n_in,
                              void* d_out, int out_size) {
    const float* emb = (const float*)d_in[0];
    const int* mask = (const int*)d_in[1];
    const int* ninst = (const int*)d_in[2];
    (void)in_sizes; (void)n_in;

    cudaFuncSetAttribute(k_pass1, cudaFuncAttributeMaxDynamicSharedMemorySize, SMEM1_BYTES);

    k_pass1<<<GRID1, T1, SMEM1_BYTES>>>(emb, mask);
    k_pass2<<<GRID2, 256>>>((const float4*)emb, (const int4*)mask,
                            ninst, (float*)d_out, out_size);
}